// round 3
// baseline (speedup 1.0000x reference)
#include <cuda_runtime.h>
#include <math.h>

#define B_   4
#define CIN  256
#define CQ   32
#define N3   13824   // 24^3
#define M3   1728    // 12^3
#define MH   (M3/2)  // 864 keys per split
#define TK   48      // key chunk

using u64 = unsigned long long;

// ---- packed f32x2 helpers (sm_103a FFMA2 path) ----
__device__ __forceinline__ u64 pack2(float lo, float hi) {
    u64 r; asm("mov.b64 %0, {%1, %2};" : "=l"(r) : "f"(lo), "f"(hi)); return r;
}
__device__ __forceinline__ void unpack2(u64 v, float& lo, float& hi) {
    asm("mov.b64 {%0, %1}, %2;" : "=f"(lo), "=f"(hi) : "l"(v));
}
__device__ __forceinline__ u64 fma2(u64 a, u64 b, u64 c) {
    u64 d; asm("fma.rn.f32x2 %0, %1, %2, %3;" : "=l"(d) : "l"(a), "l"(b), "l"(c));
    return d;
}

// Scratch (device globals; no allocation)
__device__ float g_f[B_ * N3 * CQ];        // f: [b][n][32]
__device__ float g_graw[B_ * N3 * CQ];     // pre-pool g
__device__ float g_hraw[B_ * N3 * CQ];     // pre-pool h
__device__ float g_gp[B_ * M3 * CQ];       // pooled g: [b][m][32]
__device__ float g_hp[B_ * M3 * CQ];       // pooled h
__device__ float g_accp[B_ * 2 * N3 * CQ]; // split-K partial acc
__device__ float g_lp[B_ * 2 * N3];        // split-K partial l

// ---------------------------------------------------------------------------
// Projection: one W matrix per gridDim.z (0=f, 1=g, 2=h).
// Block: 128 threads, 256 positions (2 per thread). FFMA2 inner loop.
// ---------------------------------------------------------------------------
__global__ __launch_bounds__(128, 4) void proj_kernel(
    const float* __restrict__ x,
    const float* __restrict__ Wf,
    const float* __restrict__ Wg,
    const float* __restrict__ Wh)
{
    __shared__ float xs[32][256];   // 32 KB
    __shared__ float ws[32][32];    // 4 KB  [ci][c'] transposed chunk

    const int b   = blockIdx.y;
    const int z   = blockIdx.z;
    const int n0  = blockIdx.x * 256;
    const int tid = threadIdx.x;

    const float* W = (z == 0) ? Wf : (z == 1) ? Wg : Wh;
    float* dst = (z == 0) ? g_f : (z == 1) ? g_graw : g_hraw;

    u64 acc0[16], acc1[16];
#pragma unroll
    for (int i = 0; i < 16; i++) { acc0[i] = 0ull; acc1[i] = 0ull; }

    for (int cc0 = 0; cc0 < CIN; cc0 += 32) {
        __syncthreads();
        {
            const float4* xsrc = (const float4*)(x + ((size_t)b * CIN + cc0) * N3 + n0);
            float4* xdst = (float4*)&xs[0][0];
#pragma unroll
            for (int i = 0; i < 16; i++) {
                int idx = tid + i * 128;          // 0..2047 float4s
                int row = idx >> 6;
                int c4  = idx & 63;
                xdst[idx] = xsrc[(size_t)row * (N3 / 4) + c4];
            }
        }
#pragma unroll
        for (int i = 0; i < 8; i++) {
            int idx = tid + i * 128;
            int ci = idx >> 5, cp = idx & 31;
            ws[ci][cp] = W[cp * CIN + cc0 + ci];
        }
        __syncthreads();

#pragma unroll
        for (int ci = 0; ci < 32; ci++) {
            float x0 = xs[ci][tid];
            float x1 = xs[ci][tid + 128];
            u64 xv0 = pack2(x0, x0);
            u64 xv1 = pack2(x1, x1);
            const ulonglong2* wp = (const ulonglong2*)&ws[ci][0];
#pragma unroll
            for (int c = 0; c < 8; c++) {
                ulonglong2 w = wp[c];
                acc0[2*c + 0] = fma2(xv0, w.x, acc0[2*c + 0]);
                acc0[2*c + 1] = fma2(xv0, w.y, acc0[2*c + 1]);
                acc1[2*c + 0] = fma2(xv1, w.x, acc1[2*c + 0]);
                acc1[2*c + 1] = fma2(xv1, w.y, acc1[2*c + 1]);
            }
        }
    }

    {
        ulonglong2* d0 = (ulonglong2*)(dst + ((size_t)b * N3 + n0 + tid) * CQ);
        ulonglong2* d1 = (ulonglong2*)(dst + ((size_t)b * N3 + n0 + 128 + tid) * CQ);
#pragma unroll
        for (int c = 0; c < 8; c++) {
            d0[c] = make_ulonglong2(acc0[2*c], acc0[2*c + 1]);
            d1[c] = make_ulonglong2(acc1[2*c], acc1[2*c + 1]);
        }
    }
}

// ---------------------------------------------------------------------------
// 2x2x2 max pool on graw/hraw -> gp/hp. One thread per (b, m, c').
// ---------------------------------------------------------------------------
__global__ void pool_kernel()
{
    int idx = blockIdx.x * 256 + threadIdx.x;
    const int total = B_ * M3 * CQ;
    if (idx >= total) return;
    int c = idx & 31;
    int m = (idx >> 5) % M3;
    int b = idx / (M3 * CQ);
    int md = m / 144, mh = (m / 12) % 12, mw = m % 12;

    float gmax = -INFINITY, hmax = -INFINITY;
#pragma unroll
    for (int dd = 0; dd < 2; dd++)
#pragma unroll
        for (int dh = 0; dh < 2; dh++)
#pragma unroll
            for (int dw = 0; dw < 2; dw++) {
                int n = (2*md + dd) * 576 + (2*mh + dh) * 24 + (2*mw + dw);
                size_t o = ((size_t)b * N3 + n) * CQ + c;
                gmax = fmaxf(gmax, g_graw[o]);
                hmax = fmaxf(hmax, g_hraw[o]);
            }
    size_t po = ((size_t)b * M3 + m) * CQ + c;
    g_gp[po] = gmax;
    g_hp[po] = hmax;
}

// ---------------------------------------------------------------------------
// Attention partial: split-K over keys (gridDim.z = 2), 2 queries per thread.
// No-max softmax partials: acc[32], l per (query, split). Purely additive.
// ---------------------------------------------------------------------------
__global__ __launch_bounds__(128, 3) void attn_partial(void)
{
    __shared__ float gk[TK][CQ];     // 6 KB
    __shared__ float hk[TK][CQ];     // 6 KB

    const int b   = blockIdx.y;
    const int z   = blockIdx.z;
    const int tid = threadIdx.x;
    const int q0  = blockIdx.x * 256 + tid;
    const int q1  = q0 + 128;

    u64 fq0[16], fq1[16];
    {
        const ulonglong2* f0 = (const ulonglong2*)(g_f + ((size_t)b * N3 + q0) * CQ);
        const ulonglong2* f1 = (const ulonglong2*)(g_f + ((size_t)b * N3 + q1) * CQ);
#pragma unroll
        for (int c = 0; c < 8; c++) {
            ulonglong2 v0 = f0[c], v1 = f1[c];
            fq0[2*c] = v0.x; fq0[2*c + 1] = v0.y;
            fq1[2*c] = v1.x; fq1[2*c + 1] = v1.y;
        }
    }

    u64 acc0[16], acc1[16];
#pragma unroll
    for (int i = 0; i < 16; i++) { acc0[i] = 0ull; acc1[i] = 0ull; }
    float l0 = 0.f, l1 = 0.f;

    const int kbase = z * MH;
    for (int k0 = 0; k0 < MH; k0 += TK) {
        __syncthreads();
        {
            const float4* gsrc = (const float4*)(g_gp + ((size_t)b * M3 + kbase + k0) * CQ);
            const float4* hsrc = (const float4*)(g_hp + ((size_t)b * M3 + kbase + k0) * CQ);
            float4* gdst = (float4*)&gk[0][0];
            float4* hdst = (float4*)&hk[0][0];
#pragma unroll
            for (int i = 0; i < (TK * CQ / 4) / 128; i++) {
                gdst[tid + i * 128] = gsrc[tid + i * 128];
                hdst[tid + i * 128] = hsrc[tid + i * 128];
            }
        }
        __syncthreads();

#pragma unroll 2
        for (int j = 0; j < TK; j++) {
            const ulonglong2* gp = (const ulonglong2*)&gk[j][0];
            u64 sa0 = 0ull, sb0 = 0ull, sa1 = 0ull, sb1 = 0ull;
#pragma unroll
            for (int c = 0; c < 8; c++) {
                ulonglong2 gv = gp[c];
                sa0 = fma2(fq0[2*c + 0], gv.x, sa0);
                sb0 = fma2(fq0[2*c + 1], gv.y, sb0);
                sa1 = fma2(fq1[2*c + 0], gv.x, sa1);
                sb1 = fma2(fq1[2*c + 1], gv.y, sb1);
            }
            float a0, a1, b0, b1, c0, c1, d0, d1;
            unpack2(sa0, a0, a1); unpack2(sb0, b0, b1);
            unpack2(sa1, c0, c1); unpack2(sb1, d0, d1);
            float p0 = __expf((a0 + a1) + (b0 + b1));
            float p1 = __expf((c0 + c1) + (d0 + d1));
            l0 += p0; l1 += p1;
            u64 pp0 = pack2(p0, p0);
            u64 pp1 = pack2(p1, p1);
            const ulonglong2* hp = (const ulonglong2*)&hk[j][0];
#pragma unroll
            for (int c = 0; c < 8; c++) {
                ulonglong2 hv = hp[c];
                acc0[2*c + 0] = fma2(pp0, hv.x, acc0[2*c + 0]);
                acc0[2*c + 1] = fma2(pp0, hv.y, acc0[2*c + 1]);
                acc1[2*c + 0] = fma2(pp1, hv.x, acc1[2*c + 0]);
                acc1[2*c + 1] = fma2(pp1, hv.y, acc1[2*c + 1]);
            }
        }
    }

    {
        size_t row = (size_t)(b * 2 + z) * N3;
        ulonglong2* a0 = (ulonglong2*)(g_accp + (row + q0) * CQ);
        ulonglong2* a1 = (ulonglong2*)(g_accp + (row + q1) * CQ);
#pragma unroll
        for (int c = 0; c < 8; c++) {
            a0[c] = make_ulonglong2(acc0[2*c], acc0[2*c + 1]);
            a1[c] = make_ulonglong2(acc1[2*c], acc1[2*c + 1]);
        }
        g_lp[row + q0] = l0;
        g_lp[row + q1] = l1;
    }
}

// ---------------------------------------------------------------------------
// Epilogue: combine split-K halves, normalize, Wv projection + residual.
// Block = 128 threads = 128 queries.
// ---------------------------------------------------------------------------
__global__ __launch_bounds__(128) void attn_epilogue(
    const float* __restrict__ x,
    const float* __restrict__ Wv,
    const float* __restrict__ gamma_p,
    float* __restrict__ out)
{
    __shared__ float sWv[CIN * CQ];  // 32 KB

    const int b   = blockIdx.y;
    const int tid = threadIdx.x;
    const int q   = blockIdx.x * 128 + tid;

    for (int i = tid; i < CIN * CQ; i += 128) sWv[i] = Wv[i];

    // combine partials
    u64 o2[16];
    {
        size_t r0 = (size_t)(b * 2 + 0) * N3 + q;
        size_t r1 = (size_t)(b * 2 + 1) * N3 + q;
        const float4* p0 = (const float4*)(g_accp + r0 * CQ);
        const float4* p1 = (const float4*)(g_accp + r1 * CQ);
        float inv = 1.0f / (g_lp[r0] + g_lp[r1]);
#pragma unroll
        for (int c = 0; c < 8; c++) {
            float4 v0 = p0[c];
            float4 v1 = p1[c];
            o2[2*c + 0] = pack2((v0.x + v1.x) * inv, (v0.y + v1.y) * inv);
            o2[2*c + 1] = pack2((v0.z + v1.z) * inv, (v0.w + v1.w) * inv);
        }
    }
    __syncthreads();

    const float gma = *gamma_p;
    size_t xb = (size_t)b * CIN * N3 + q;
#pragma unroll 4
    for (int cc = 0; cc < CIN; cc++) {
        const ulonglong2* wp = (const ulonglong2*)&sWv[cc * CQ];
        u64 ea = 0ull, eb = 0ull;
#pragma unroll
        for (int c = 0; c < 8; c++) {
            ulonglong2 w = wp[c];
            ea = fma2(o2[2*c + 0], w.x, ea);
            eb = fma2(o2[2*c + 1], w.y, eb);
        }
        float a0, a1, b0, b1;
        unpack2(ea, a0, a1);
        unpack2(eb, b0, b1);
        float s = (a0 + a1) + (b0 + b1);
        size_t o = xb + (size_t)cc * N3;
        out[o] = fmaf(gma, s, x[o]);
    }
}

// ---------------------------------------------------------------------------
extern "C" void kernel_launch(void* const* d_in, const int* in_sizes, int n_in,
                              void* d_out, int out_size)
{
    const float* x     = (const float*)d_in[0];
    const float* Wf    = (const float*)d_in[1];
    const float* Wg    = (const float*)d_in[2];
    const float* Wh    = (const float*)d_in[3];
    const float* Wv    = (const float*)d_in[4];
    const float* gamma = (const float*)d_in[5];
    float* out = (float*)d_out;

    dim3 pgrid(N3 / 256, B_, 3);
    proj_kernel<<<pgrid, 128>>>(x, Wf, Wg, Wh);

    int ptotal = B_ * M3 * CQ;
    pool_kernel<<<(ptotal + 255) / 256, 256>>>();

    dim3 agrid(N3 / 256, B_, 2);
    attn_partial<<<agrid, 128>>>();

    dim3 egrid(N3 / 128, B_);
    attn_epilogue<<<egrid, 128>>>(x, Wv, gamma, out);
}